// round 11
// baseline (speedup 1.0000x reference)
#include <cuda_runtime.h>

#define N_NODES 50000
#define N_EDGES 1600000
#define HID 128
#define TILE 64
#define THREADS 256
#define H1_STRIDE 66   // padded row stride (floats), even -> LDS.64 stays 8B aligned

// Scratch (device globals: allocation-free per harness rules)
__device__ float g_gsq[N_NODES];
__device__ float g_msg[N_NODES];

typedef unsigned long long u64;

__device__ __forceinline__ u64 pack2(float lo, float hi) {
    u64 r; asm("mov.b64 %0, {%1, %2};" : "=l"(r) : "f"(lo), "f"(hi)); return r;
}
__device__ __forceinline__ void unpack2(u64 v, float& lo, float& hi) {
    asm("mov.b64 {%0, %1}, %2;" : "=f"(lo), "=f"(hi) : "l"(v));
}
// Blackwell packed fp32x2 FMA (PTX ISA 8.6, sm_100+): 2x FFMA throughput
__device__ __forceinline__ u64 ffma2(u64 a, u64 b, u64 c) {
    u64 d; asm("fma.rn.f32x2 %0, %1, %2, %3;" : "=l"(d) : "l"(a), "l"(b), "l"(c)); return d;
}

// Accurate fast tanh on the (idle) MUFU pipe:
//   tanh(x) = 1 - 2/(exp(2x)+1),  exp(2x) = 2^(2x*log2(e))
// ex2.approx / rcp.approx are ~2-ulp -> abs error ~1e-7..1e-6 (NOT tanh.approx's 1e-4).
// Saturates correctly: x->+inf: ex2->inf, rcp->0, t->1; x->-inf: ex2->0, t->-1.
__device__ __forceinline__ float fast_tanh(float x) {
    float e, r;
    asm("ex2.approx.f32 %0, %1;" : "=f"(e) : "f"(x * 2.8853900817779268f));
    asm("rcp.approx.f32 %0, %1;" : "=f"(r) : "f"(e + 1.0f));
    return fmaf(-2.0f, r, 1.0f);
}

// One block = 64 nodes. 3-layer MLP (IN -> 128 tanh -> 128 tanh -> 1).
// Column mapping for layer 2/3: j = 4*lane + q (q=0..3) so w1/b1/w2 load as float4.
// MODE 0: g_phi path -> writes g_gsq[n] = g^2 and zeroes g_msg[n].
// MODE 1: f_theta path -> reads g_msg, writes out[n].
template<int IN, int MODE>
__global__ __launch_bounds__(THREADS)
void mlp_kernel(const float* __restrict__ v,
                const float* __restrict__ a,
                const float* __restrict__ exc,
                const float* __restrict__ w0, const float* __restrict__ b0,
                const float* __restrict__ w1, const float* __restrict__ b1,
                const float* __restrict__ w2, const float* __restrict__ b2,
                float* __restrict__ out)
{
    // h1 stored transposed: s_h1t[k * H1_STRIDE + n]  (k = hidden unit, n = local node)
    __shared__ __align__(16) float s_h1t[HID * H1_STRIDE];
    __shared__ float s_x[TILE][IN];

    const int t = threadIdx.x;
    const int node0 = blockIdx.x * TILE;

    // ---- stage node inputs into smem ----
    for (int i = t; i < TILE * IN; i += THREADS) {
        int n = i / IN, c = i % IN;
        int gn = node0 + n;
        float val = 0.f;
        if (gn < N_NODES) {
            if (c == 0)      val = v[gn];
            else if (c == 1) val = a[2 * gn];
            else if (c == 2) val = a[2 * gn + 1];
            else if (c == 3) val = g_msg[gn];       // only IN==5
            else             val = exc[gn];          // only IN==5
        }
        s_x[n][c] = val;
    }
    __syncthreads();

    // ---- layer 1: h1[n][j] = tanh(b0[j] + sum_c x[n][c]*w0[c][j]) ----
    for (int i = t; i < TILE * HID; i += THREADS) {
        int n = i >> 7, j = i & 127;
        float acc = b0[j];
        #pragma unroll
        for (int c = 0; c < IN; c++) acc = fmaf(s_x[n][c], w0[c * HID + j], acc);
        s_h1t[j * H1_STRIDE + n] = fast_tanh(acc);
    }
    __syncthreads();

    // ---- layer 2 (128x128 GEMM, f32x2 over node pairs) + layer 3 ----
    const int warp = t >> 5, lane = t & 31;
    const int nb = warp * 8;                    // this warp handles local nodes nb..nb+7
    // acc[i][q]: node pair (nb+2i, nb+2i+1) x column j = 4*lane + q
    u64 acc[4][4];
    {
        float4 b1v = ((const float4*)b1)[lane];
        const float* bq = (const float*)&b1v;
        #pragma unroll
        for (int q = 0; q < 4; q++) {
            u64 p = pack2(bq[q], bq[q]);
            #pragma unroll
            for (int i = 0; i < 4; i++) acc[i][q] = p;
        }
    }

    const float4* w1v = (const float4*)w1;      // w1[k][4*lane + q] = w1v[k*32 + lane].q
    #pragma unroll 4
    for (int k = 0; k < HID; k++) {
        float4 w = w1v[k * 32 + lane];           // one LDG.128: 4 columns, L1-resident
        u64 wp[4];
        wp[0] = pack2(w.x, w.x); wp[1] = pack2(w.y, w.y);
        wp[2] = pack2(w.z, w.z); wp[3] = pack2(w.w, w.w);
        const u64* hrow = (const u64*)&s_h1t[k * H1_STRIDE + nb]; // aligned: even stride
        #pragma unroll
        for (int i = 0; i < 4; i++) {
            u64 h2 = hrow[i];                    // LDS.64: 2 nodes' h1[k]
            #pragma unroll
            for (int q = 0; q < 4; q++) acc[i][q] = ffma2(h2, wp[q], acc[i][q]);
        }
    }

    // ---- layer 3: scalar head, warp-reduce over j ----
    const float b2v = b2[0];
    float4 w2v = ((const float4*)w2)[lane];
    const float* w2q = (const float*)&w2v;
    #pragma unroll
    for (int i = 0; i < 4; i++) {
        float p0 = 0.f, p1 = 0.f;
        #pragma unroll
        for (int q = 0; q < 4; q++) {
            float lo, hi; unpack2(acc[i][q], lo, hi);
            p0 = fmaf(fast_tanh(lo), w2q[q], p0);
            p1 = fmaf(fast_tanh(hi), w2q[q], p1);
        }
        #pragma unroll
        for (int o = 16; o > 0; o >>= 1) {
            p0 += __shfl_xor_sync(0xffffffffu, p0, o);
            p1 += __shfl_xor_sync(0xffffffffu, p1, o);
        }
        if (lane == 0) {
            int n0 = node0 + nb + 2 * i;
            int n1 = n0 + 1;
            if (MODE == 0) {
                if (n0 < N_NODES) { float g = p0 + b2v; g_gsq[n0] = g * g; g_msg[n0] = 0.f; }
                if (n1 < N_NODES) { float g = p1 + b2v; g_gsq[n1] = g * g; g_msg[n1] = 0.f; }
            } else {
                if (n0 < N_NODES) out[n0] = p0 + b2v;
                if (n1 < N_NODES) out[n1] = p1 + b2v;
            }
        }
    }
}

// msg[dst] += W[e] * gsq[src]  (gsq/msg are 200KB each -> L2-resident)
// 4 edges per thread, vectorized loads. N_EDGES % 4 == 0.
__global__ __launch_bounds__(256)
void edge_kernel(const int* __restrict__ src,
                 const int* __restrict__ dst,
                 const float* __restrict__ W)
{
    int i = blockIdx.x * 256 + threadIdx.x;
    if (i < N_EDGES / 4) {
        int4   s = ((const int4*)src)[i];
        int4   d = ((const int4*)dst)[i];
        float4 w = ((const float4*)W)[i];
        atomicAdd(&g_msg[d.x], w.x * __ldg(&g_gsq[s.x]));
        atomicAdd(&g_msg[d.y], w.y * __ldg(&g_gsq[s.y]));
        atomicAdd(&g_msg[d.z], w.z * __ldg(&g_gsq[s.z]));
        atomicAdd(&g_msg[d.w], w.w * __ldg(&g_gsq[s.w]));
    }
}

extern "C" void kernel_launch(void* const* d_in, const int* in_sizes, int n_in,
                              void* d_out, int out_size)
{
    const float* v    = (const float*)d_in[0];
    const float* exc  = (const float*)d_in[1];
    const int*   esrc = (const int*)  d_in[2];
    const int*   edst = (const int*)  d_in[3];
    const float* a    = (const float*)d_in[4];
    const float* W    = (const float*)d_in[5];
    const float* g0w  = (const float*)d_in[6];
    const float* g0b  = (const float*)d_in[7];
    const float* g1w  = (const float*)d_in[8];
    const float* g1b  = (const float*)d_in[9];
    const float* g2w  = (const float*)d_in[10];
    const float* g2b  = (const float*)d_in[11];
    const float* f0w  = (const float*)d_in[12];
    const float* f0b  = (const float*)d_in[13];
    const float* f1w  = (const float*)d_in[14];
    const float* f1b  = (const float*)d_in[15];
    const float* f2w  = (const float*)d_in[16];
    const float* f2b  = (const float*)d_in[17];

    const int mlp_blocks = (N_NODES + TILE - 1) / TILE;   // 782

    // 1) per-node g_phi^2 (+ zero msg)
    mlp_kernel<3, 0><<<mlp_blocks, THREADS>>>(v, a, exc, g0w, g0b, g1w, g1b, g2w, g2b, nullptr);
    // 2) edge scatter
    edge_kernel<<<(N_EDGES / 4 + 255) / 256, 256>>>(esrc, edst, W);
    // 3) per-node f_theta -> output
    mlp_kernel<5, 1><<<mlp_blocks, THREADS>>>(v, a, exc, f0w, f0b, f1w, f1b, f2w, f2b, (float*)d_out);
}

// round 16
// speedup vs baseline: 1.0741x; 1.0741x over previous
#include <cuda_runtime.h>

#define N_NODES 50000
#define N_EDGES 1600000
#define HID 128
#define TILE 64          // nodes per block (8 per warp)
#define THREADS 256
#define HSTRIDE 10       // per-k stride (floats) in a warp's h1 region: even -> LDS.64 aligned,
                         // (10*lane)%32 -> only 2-way STS conflict
#define WREGION (HID * HSTRIDE)   // 1280 floats = 5KB per warp

// Scratch (device globals: allocation-free per harness rules)
__device__ float g_gsq[N_NODES];
__device__ float g_msg[N_NODES];

typedef unsigned long long u64;

__device__ __forceinline__ u64 pack2(float lo, float hi) {
    u64 r; asm("mov.b64 %0, {%1, %2};" : "=l"(r) : "f"(lo), "f"(hi)); return r;
}
__device__ __forceinline__ void unpack2(u64 v, float& lo, float& hi) {
    asm("mov.b64 {%0, %1}, %2;" : "=f"(lo), "=f"(hi) : "l"(v));
}
// Blackwell packed fp32x2 FMA (PTX ISA 8.6, sm_100+): 2x FFMA throughput
__device__ __forceinline__ u64 ffma2(u64 a, u64 b, u64 c) {
    u64 d; asm("fma.rn.f32x2 %0, %1, %2, %3;" : "=l"(d) : "l"(a), "l"(b), "l"(c)); return d;
}

// Accurate fast tanh using the idle MUFU pipe (~2-ulp ex2/rcp, NOT tanh.approx):
//   tanh(x) = 1 - 2/(exp(2x)+1)
__device__ __forceinline__ float fast_tanh(float x) {
    float e, r;
    asm("ex2.approx.f32 %0, %1;" : "=f"(e) : "f"(x * 2.8853900817779268f));
    asm("rcp.approx.f32 %0, %1;" : "=f"(r) : "f"(e + 1.0f));
    return fmaf(-2.0f, r, 1.0f);
}

// Warp-autonomous 3-layer MLP (IN -> 128 tanh -> 128 tanh -> 1).
// Each warp owns 8 consecutive nodes end-to-end: stages inputs, computes its own
// h1 tile into private smem, runs the 8x128x128 f32x2 GEMM, and the scalar head.
// NO __syncthreads anywhere -> no phase drain, fma pipe stays fed.
// MODE 0: g_phi path -> writes g_gsq[n] = g^2 and zeroes g_msg[n].
// MODE 1: f_theta path -> reads g_msg, writes out[n].
template<int IN, int MODE>
__global__ __launch_bounds__(THREADS)
void mlp_kernel(const float* __restrict__ v,
                const float* __restrict__ a,
                const float* __restrict__ exc,
                const float* __restrict__ w0, const float* __restrict__ b0,
                const float* __restrict__ w1, const float* __restrict__ b1,
                const float* __restrict__ w2, const float* __restrict__ b2,
                float* __restrict__ out)
{
    __shared__ __align__(16) float s_h1[(THREADS / 32) * WREGION];   // 40KB

    const int t = threadIdx.x, warp = t >> 5, lane = t & 31;
    const int nb = blockIdx.x * TILE + warp * 8;     // first node of this warp
    float* hw = &s_h1[warp * WREGION];

    // ---- stage this warp's 8 nodes' inputs: lane n (n<8) holds node nb+n ----
    float xv = 0.f, xa0 = 0.f, xa1 = 0.f, xm = 0.f, xe = 0.f;
    if (lane < 8) {
        int gn = nb + lane;
        if (gn < N_NODES) {
            xv  = v[gn];
            xa0 = a[2 * gn];
            xa1 = a[2 * gn + 1];
            if (IN == 5) { xm = g_msg[gn]; xe = exc[gn]; }
        }
    }

    // ---- layer 1 (warp-local): h1[k][n] = tanh(b0[k] + sum_c x[n][c]*w0[c][k]) ----
    #pragma unroll
    for (int kk = 0; kk < 4; kk++) {
        const int k = kk * 32 + lane;
        float bb = b0[k];
        float wc[IN];
        #pragma unroll
        for (int c = 0; c < IN; c++) wc[c] = w0[c * HID + k];
        #pragma unroll
        for (int n = 0; n < 8; n++) {
            float acc = bb;
            acc = fmaf(__shfl_sync(0xffffffffu, xv,  n), wc[0], acc);
            acc = fmaf(__shfl_sync(0xffffffffu, xa0, n), wc[1], acc);
            acc = fmaf(__shfl_sync(0xffffffffu, xa1, n), wc[2], acc);
            if (IN == 5) {
                acc = fmaf(__shfl_sync(0xffffffffu, xm, n), wc[3], acc);
                acc = fmaf(__shfl_sync(0xffffffffu, xe, n), wc[4], acc);
            }
            hw[k * HSTRIDE + n] = fast_tanh(acc);
        }
    }
    __syncwarp();    // only sync in the kernel: lanes exchange h1 through smem

    // ---- layer 2: 8x128x128 GEMM, f32x2 over node pairs; j = 4*lane + q ----
    u64 acc[4][4];
    {
        float4 b1v = ((const float4*)b1)[lane];
        const float* bq = (const float*)&b1v;
        #pragma unroll
        for (int q = 0; q < 4; q++) {
            u64 p = pack2(bq[q], bq[q]);
            #pragma unroll
            for (int i = 0; i < 4; i++) acc[i][q] = p;
        }
    }

    const float4* w1v = (const float4*)w1;      // w1[k][4*lane+q], one LDG.128/k, L1-resident
    #pragma unroll 4
    for (int k = 0; k < HID; k++) {
        float4 w = w1v[k * 32 + lane];
        u64 wp[4];
        wp[0] = pack2(w.x, w.x); wp[1] = pack2(w.y, w.y);
        wp[2] = pack2(w.z, w.z); wp[3] = pack2(w.w, w.w);
        const u64* hrow = (const u64*)&hw[k * HSTRIDE];   // even offset -> aligned LDS.64
        #pragma unroll
        for (int i = 0; i < 4; i++) {
            u64 h2 = hrow[i];                  // broadcast LDS.64: nodes (2i, 2i+1)
            #pragma unroll
            for (int q = 0; q < 4; q++) acc[i][q] = ffma2(h2, wp[q], acc[i][q]);
        }
    }

    // ---- layer 3: scalar head, warp-reduce over j ----
    const float b2v = b2[0];
    float4 w2v = ((const float4*)w2)[lane];
    const float* w2q = (const float*)&w2v;
    #pragma unroll
    for (int i = 0; i < 4; i++) {
        float p0 = 0.f, p1 = 0.f;
        #pragma unroll
        for (int q = 0; q < 4; q++) {
            float lo, hi; unpack2(acc[i][q], lo, hi);
            p0 = fmaf(fast_tanh(lo), w2q[q], p0);
            p1 = fmaf(fast_tanh(hi), w2q[q], p1);
        }
        #pragma unroll
        for (int o = 16; o > 0; o >>= 1) {
            p0 += __shfl_xor_sync(0xffffffffu, p0, o);
            p1 += __shfl_xor_sync(0xffffffffu, p1, o);
        }
        if (lane == 0) {
            int n0 = nb + 2 * i;
            int n1 = n0 + 1;
            if (MODE == 0) {
                if (n0 < N_NODES) { float g = p0 + b2v; g_gsq[n0] = g * g; g_msg[n0] = 0.f; }
                if (n1 < N_NODES) { float g = p1 + b2v; g_gsq[n1] = g * g; g_msg[n1] = 0.f; }
            } else {
                if (n0 < N_NODES) out[n0] = p0 + b2v;
                if (n1 < N_NODES) out[n1] = p1 + b2v;
            }
        }
    }
}

// msg[dst] += W[e] * gsq[src]  (gsq/msg are 200KB each -> L2-resident)
// 4 edges per thread, vectorized loads. N_EDGES % 4 == 0.
__global__ __launch_bounds__(256)
void edge_kernel(const int* __restrict__ src,
                 const int* __restrict__ dst,
                 const float* __restrict__ W)
{
    int i = blockIdx.x * 256 + threadIdx.x;
    if (i < N_EDGES / 4) {
        int4   s = ((const int4*)src)[i];
        int4   d = ((const int4*)dst)[i];
        float4 w = ((const float4*)W)[i];
        atomicAdd(&g_msg[d.x], w.x * __ldg(&g_gsq[s.x]));
        atomicAdd(&g_msg[d.y], w.y * __ldg(&g_gsq[s.y]));
        atomicAdd(&g_msg[d.z], w.z * __ldg(&g_gsq[s.z]));
        atomicAdd(&g_msg[d.w], w.w * __ldg(&g_gsq[s.w]));
    }
}

extern "C" void kernel_launch(void* const* d_in, const int* in_sizes, int n_in,
                              void* d_out, int out_size)
{
    const float* v    = (const float*)d_in[0];
    const float* exc  = (const float*)d_in[1];
    const int*   esrc = (const int*)  d_in[2];
    const int*   edst = (const int*)  d_in[3];
    const float* a    = (const float*)d_in[4];
    const float* W    = (const float*)d_in[5];
    const float* g0w  = (const float*)d_in[6];
    const float* g0b  = (const float*)d_in[7];
    const float* g1w  = (const float*)d_in[8];
    const float* g1b  = (const float*)d_in[9];
    const float* g2w  = (const float*)d_in[10];
    const float* g2b  = (const float*)d_in[11];
    const float* f0w  = (const float*)d_in[12];
    const float* f0b  = (const float*)d_in[13];
    const float* f1w  = (const float*)d_in[14];
    const float* f1b  = (const float*)d_in[15];
    const float* f2w  = (const float*)d_in[16];
    const float* f2b  = (const float*)d_in[17];

    const int mlp_blocks = (N_NODES + TILE - 1) / TILE;   // 782

    // 1) per-node g_phi^2 (+ zero msg)
    mlp_kernel<3, 0><<<mlp_blocks, THREADS>>>(v, a, exc, g0w, g0b, g1w, g1b, g2w, g2b, nullptr);
    // 2) edge scatter
    edge_kernel<<<(N_EDGES / 4 + 255) / 256, 256>>>(esrc, edst, W);
    // 3) per-node f_theta -> output
    mlp_kernel<5, 1><<<mlp_blocks, THREADS>>>(v, a, exc, f0w, f0b, f1w, f1b, f2w, f2b, (float*)d_out);
}